// round 1
// baseline (speedup 1.0000x reference)
#include <cuda_runtime.h>

// Spline / thin-plate RBF (order 3) over a 1024x1024 grid, batch 4, M=16.
// out[b, y, x] = sum_m ( max((x-tx_m)^2 + (y-ty_m)^2, 1e-10) )^{3/2} * ww[m]/2^40
//              + x*vw[0] + y*vw[1] + vw[2]
// All batches identical (weights broadcast from batch dim 1); compute once,
// store 4x.

#define WDIM 1024
#define HDIM 1024
#define MPTS 16

__device__ __forceinline__ float sqrt_approx(float v) {
    float r;
    asm("sqrt.approx.f32 %0, %1;" : "=f"(r) : "f"(v));
    return r;
}

__global__ void __launch_bounds__(256) spline_kernel(
    const float* __restrict__ train_points,  // [16,2] in [0,1]
    const float* __restrict__ ww,            // [16]
    const float* __restrict__ vw,            // [3]
    float* __restrict__ out,                 // [B, 1024, 1024]
    int B)
{
    __shared__ float stx[MPTS], sty[MPTS], sw[MPTS], sv[3];
    const int t = threadIdx.x;
    if (t < MPTS) {
        stx[t] = train_points[2 * t]     * 1024.0f;
        sty[t] = train_points[2 * t + 1] * 1024.0f;
        // ww / (W*W*H*H) = ww * 2^-40 (exact)
        sw[t]  = ww[t] * (1.0f / 1099511627776.0f);
    }
    if (t < 3) sv[t] = vw[t];
    __syncthreads();

    const int y  = blockIdx.x;        // row, 0..1023
    const int x0 = t << 2;            // 4 consecutive x per thread
    const float fy = (float)y;
    const float fx0 = (float)x0;
    const float fx1 = fx0 + 1.0f;
    const float fx2 = fx0 + 2.0f;
    const float fx3 = fx0 + 3.0f;

    float a0 = 0.f, a1 = 0.f, a2 = 0.f, a3 = 0.f;

#pragma unroll
    for (int m = 0; m < MPTS; ++m) {
        const float tx = stx[m];
        const float dy = fy - sty[m];
        const float dy2 = dy * dy;
        const float w = sw[m];

        float dx, r;
        dx = fx0 - tx; r = fmaf(dx, dx, dy2); r = fmaxf(r, 1e-10f);
        a0 = fmaf(r * sqrt_approx(r), w, a0);
        dx = fx1 - tx; r = fmaf(dx, dx, dy2); r = fmaxf(r, 1e-10f);
        a1 = fmaf(r * sqrt_approx(r), w, a1);
        dx = fx2 - tx; r = fmaf(dx, dx, dy2); r = fmaxf(r, 1e-10f);
        a2 = fmaf(r * sqrt_approx(r), w, a2);
        dx = fx3 - tx; r = fmaf(dx, dx, dy2); r = fmaxf(r, 1e-10f);
        a3 = fmaf(r * sqrt_approx(r), w, a3);
    }

    const float linc = fmaf(fy, sv[1], sv[2]);  // y*v1 + v2
    float4 v;
    v.x = a0 + fmaf(fx0, sv[0], linc);
    v.y = a1 + fmaf(fx1, sv[0], linc);
    v.z = a2 + fmaf(fx2, sv[0], linc);
    v.w = a3 + fmaf(fx3, sv[0], linc);

    const size_t off = (size_t)y * WDIM + x0;
    const size_t plane = (size_t)WDIM * HDIM;
#pragma unroll 4
    for (int b = 0; b < B; ++b) {
        *reinterpret_cast<float4*>(out + b * plane + off) = v;
    }
}

extern "C" void kernel_launch(void* const* d_in, const int* in_sizes, int n_in,
                              void* d_out, int out_size)
{
    // inputs per metadata order: x [B,1024,1024,1] (unused values, gives B),
    // train_points [1,16,2], ww [1,16,1], vw [1,3,1]
    const float* train_points = (const float*)d_in[1];
    const float* ww           = (const float*)d_in[2];
    const float* vw           = (const float*)d_in[3];
    float* out = (float*)d_out;

    const int B = in_sizes[0] / (WDIM * HDIM);  // = 4

    dim3 grid(HDIM);   // one block per row
    dim3 block(256);   // 4 x-values per thread
    spline_kernel<<<grid, block>>>(train_points, ww, vw, out, B);
}

// round 2
// speedup vs baseline: 1.2152x; 1.2152x over previous
#include <cuda_runtime.h>

// Thin-plate spline (order 3), 1024x1024 grid, batch 4 (all batches identical).
//   out[b,y,x] = sum_m phi((x-tx_m)^2 + (y-ty_m)^2) * ww_m/2^40  +  v0*x + v1*y + v2
//   phi(r2) = r2^{3/2}
//
// The RBF field is C^2 with tiny curvature (|f''| ~ 1.4e-7 absolute), so we
// evaluate it on a stride-4 coarse grid and bilinearly interpolate (abs err
// ~6e-7, vs output norm O(100..1000) => rel err ~1e-9..1e-7, budget 1e-3).
// The linear term is applied exactly. This cuts MUFU (sqrt) work 16x and FMA
// work ~8x; the kernel becomes store-bound.

#define WDIM 1024
#define HDIM 1024
#define MPTS 16
#define CCOLS 257   // coarse columns: x = 0,4,...,1024

__device__ __forceinline__ float sqrt_approx(float v) {
    float r;
    asm("sqrt.approx.f32 %0, %1;" : "=f"(r) : "f"(v));
    return r;
}

__global__ void __launch_bounds__(1024, 2) spline_kernel(
    const float* __restrict__ train_points,  // [16,2] in [0,1]
    const float* __restrict__ ww,            // [16]
    const float* __restrict__ vw,            // [3]
    float* __restrict__ out,                 // [B, 1024, 1024]
    int B)
{
    __shared__ float stx[MPTS], sty[MPTS], sw[MPTS], sv[3];
    __shared__ float g[2][CCOLS];            // coarse RBF rows at y0 and y0+4

    const int t = threadIdx.x;
    const int y0 = blockIdx.x << 2;          // this block covers rows y0..y0+3

    // ---- phase 0: preprocess constants into smem ----
    if (t < MPTS) {
        stx[t] = train_points[2 * t]     * 1024.0f;
        sty[t] = train_points[2 * t + 1] * 1024.0f;
        sw[t]  = ww[t] * (1.0f / 1099511627776.0f);   // ww / (W^2 H^2) = ww * 2^-40
    } else if (t < MPTS + 3) {
        sv[t - MPTS] = vw[t - MPTS];
    }
    __syncthreads();

    // ---- phase 1: coarse RBF rows (2 x 257 samples, x-stride 4) ----
    if (t < 2 * CCOLS) {
        const int row = (t >= CCOLS) ? 1 : 0;
        const int col = t - row * CCOLS;
        const float fx = (float)(col << 2);
        const float fy = (float)(y0 + (row << 2));
        float acc = 0.0f;
#pragma unroll 1
        for (int m = 0; m < MPTS; ++m) {
            const float dx = fx - stx[m];
            const float dy = fy - sty[m];
            const float r2 = fmaf(dx, dx, dy * dy);
            const float s  = sqrt_approx(r2);
            acc = fmaf(r2 * sw[m], s, acc);   // + r2^{3/2} * w
        }
        g[row][col] = acc;
    }
    __syncthreads();

    // ---- phase 2: bilinear interp + exact linear term + stores ----
    const int rl   = t >> 8;          // 0..3: row within group
    const int lane = t & 255;         // coarse cell index (= x0/4)
    const int y    = y0 + rl;
    const int x0   = lane << 2;
    const float fyf = 0.25f * (float)rl;

    const float gT0 = g[0][lane];
    const float gT1 = g[0][lane + 1];
    const float gB0 = g[1][lane];
    const float gB1 = g[1][lane + 1];

    const float gL = fmaf(gB0 - gT0, fyf, gT0);        // rbf at (x0,   y)
    const float gR = fmaf(gB1 - gT1, fyf, gT1);        // rbf at (x0+4, y)
    const float dg = (gR - gL) * 0.25f;                // rbf x-slope per pixel

    const float v0 = sv[0], v1 = sv[1], v2 = sv[2];
    const float base  = gL + fmaf((float)y, v1, v2) + (float)x0 * v0;
    const float slope = dg + v0;                       // combined per-pixel x-step

    float4 v;
    v.x = base;
    v.y = base + slope;
    v.z = fmaf(slope, 2.0f, base);
    v.w = fmaf(slope, 3.0f, base);

    const size_t off   = (size_t)y * WDIM + x0;
    const size_t plane = (size_t)WDIM * HDIM;
#pragma unroll 4
    for (int b = 0; b < B; ++b) {
        *reinterpret_cast<float4*>(out + b * plane + off) = v;
    }
}

extern "C" void kernel_launch(void* const* d_in, const int* in_sizes, int n_in,
                              void* d_out, int out_size)
{
    // inputs: x [B,1024,1024,1] (shape only), train_points [1,16,2],
    //         ww [1,16,1], vw [1,3,1]
    const float* train_points = (const float*)d_in[1];
    const float* ww           = (const float*)d_in[2];
    const float* vw           = (const float*)d_in[3];
    float* out = (float*)d_out;

    const int B = in_sizes[0] / (WDIM * HDIM);  // = 4

    dim3 grid(HDIM / 4);   // 256 blocks, each covers 4 rows
    dim3 block(1024);
    spline_kernel<<<grid, block>>>(train_points, ww, vw, out, B);
}